// round 11
// baseline (speedup 1.0000x reference)
#include <cuda_runtime.h>
#include <math.h>

// Problem constants (fixed shapes from reference): x[4,2048,1024], weights [1024,1024]
#define BB   4
#define SS   2048
#define DD   1024
#define HALF (DD / 2)

// ---------------------------------------------------------------------------
// Scratch (device globals — no cudaMalloc allowed)
// ---------------------------------------------------------------------------
__device__ float g_Q[BB * SS * DD];
__device__ float g_K[BB * SS * DD];
__device__ float g_V[BB * SS * DD];
__device__ float g_O[BB * SS * DD];
__device__ float g_P[(long)BB * SS * SS];   // attention scores / probs
__device__ float g_cos[SS * HALF];
__device__ float g_sin[SS * HALF];

// ---------------------------------------------------------------------------
// RoPE cos/sin tables.  grid = SS, block = HALF
// ---------------------------------------------------------------------------
__global__ void rope_table_kernel(float* __restrict__ ct, float* __restrict__ st) {
    int s = blockIdx.x;
    int p = threadIdx.x;                       // pair index 0..511
    double inv = exp(-((double)(2 * p) / (double)DD) * log(10000.0));
    double ang = (double)s * inv;
    ct[s * HALF + p] = (float)cos(ang);
    st[s * HALF + p] = (float)sin(ang);
}

// ---------------------------------------------------------------------------
// Apply interleaved RoPE to Q and K in place.  grid = BB*SS, block = HALF
// ---------------------------------------------------------------------------
__global__ void rope_apply_kernel(float* __restrict__ q, float* __restrict__ k,
                                  const float* __restrict__ ct,
                                  const float* __restrict__ st) {
    int s = blockIdx.x & (SS - 1);
    long off = (long)blockIdx.x * DD + 2 * threadIdx.x;
    float c  = ct[s * HALF + threadIdx.x];
    float sn = st[s * HALF + threadIdx.x];
    float2 qv = *(float2*)(q + off);
    float2 kv = *(float2*)(k + off);
    float2 qo = make_float2(qv.x * c - qv.y * sn, qv.x * sn + qv.y * c);
    float2 ko = make_float2(kv.x * c - kv.y * sn, kv.x * sn + kv.y * c);
    *(float2*)(q + off) = qo;
    *(float2*)(k + off) = ko;
}

// ---------------------------------------------------------------------------
// Row softmax over length SS.  grid = BB*SS rows, block = 256 (each thread 8)
// ---------------------------------------------------------------------------
__global__ void softmax_kernel(float* __restrict__ P) {
    float* row = P + (long)blockIdx.x * SS;
    int t = threadIdx.x;
    float v[8];
    float m = -1e30f;
#pragma unroll
    for (int j = 0; j < 8; j++) {
        v[j] = row[t + 256 * j];
        m = fmaxf(m, v[j]);
    }
    __shared__ float red[8];
#pragma unroll
    for (int o = 16; o > 0; o >>= 1)
        m = fmaxf(m, __shfl_xor_sync(0xffffffffu, m, o));
    if ((t & 31) == 0) red[t >> 5] = m;
    __syncthreads();
    m = red[0];
#pragma unroll
    for (int i = 1; i < 8; i++) m = fmaxf(m, red[i]);

    float sum = 0.f;
#pragma unroll
    for (int j = 0; j < 8; j++) {
        v[j] = expf(v[j] - m);
        sum += v[j];
    }
#pragma unroll
    for (int o = 16; o > 0; o >>= 1)
        sum += __shfl_xor_sync(0xffffffffu, sum, o);
    __syncthreads();                 // all max-reads of red[] done
    if ((t & 31) == 0) red[t >> 5] = sum;
    __syncthreads();
    sum = 0.f;
#pragma unroll
    for (int i = 0; i < 8; i++) sum += red[i];
    float inv = 1.0f / sum;
#pragma unroll
    for (int j = 0; j < 8; j++) row[t + 256 * j] = v[j] * inv;
}

// ---------------------------------------------------------------------------
// 128x128x8 register-blocked SGEMM, 256 threads, 8x8 micro-tile per thread.
//   BT = true : C[M,N] = alpha * A[M,K] @ B[N,K]^T   (both K-contiguous)
//   BT = false: C[M,N] = alpha * A[M,K] @ B[K,N]     (B is N-contiguous)
// All of M, N divisible by 128; K divisible by 8.
// grid = (N/128, M/128, batch)
// ---------------------------------------------------------------------------
template <bool BT>
__global__ void __launch_bounds__(256)
sgemm_kernel(const float* __restrict__ A, const float* __restrict__ Bm,
             float* __restrict__ C, int M, int N, int K,
             long sA, long sB, long sC, float alpha) {
    A  += (long)blockIdx.z * sA;
    Bm += (long)blockIdx.z * sB;
    C  += (long)blockIdx.z * sC;
    const int m0 = blockIdx.y * 128;
    const int n0 = blockIdx.x * 128;

    __shared__ float As[8][132];   // transposed tile [k][m], padded
    __shared__ float Bs[8][132];   // [k][n], padded

    const int t    = threadIdx.x;
    const int aRow = t >> 1;           // 0..127
    const int aCol = (t & 1) * 4;      // 0 or 4
    const int bRowNN = t >> 5;         // 0..7
    const int bColNN = (t & 31) * 4;   // 0..124
    const int tx = t & 15;
    const int ty = t >> 4;

    float acc[8][8];
#pragma unroll
    for (int i = 0; i < 8; i++)
#pragma unroll
        for (int j = 0; j < 8; j++) acc[i][j] = 0.f;

    const float* Aptr = A + (long)(m0 + aRow) * K + aCol;
    const float* Bptr;
    if (BT) Bptr = Bm + (long)(n0 + aRow) * K + aCol;
    else    Bptr = Bm + (long)bRowNN * N + n0 + bColNN;

    for (int kb = 0; kb < K; kb += 8) {
        float4 av = *(const float4*)(Aptr + kb);
        As[aCol + 0][aRow] = av.x;
        As[aCol + 1][aRow] = av.y;
        As[aCol + 2][aRow] = av.z;
        As[aCol + 3][aRow] = av.w;
        if (BT) {
            float4 bv = *(const float4*)(Bptr + kb);
            Bs[aCol + 0][aRow] = bv.x;
            Bs[aCol + 1][aRow] = bv.y;
            Bs[aCol + 2][aRow] = bv.z;
            Bs[aCol + 3][aRow] = bv.w;
        } else {
            float4 bv = *(const float4*)(Bptr + (long)kb * N);
            *(float4*)&Bs[bRowNN][bColNN] = bv;
        }
        __syncthreads();
#pragma unroll
        for (int k = 0; k < 8; k++) {
            float4 a0 = *(const float4*)&As[k][ty * 8];
            float4 a1 = *(const float4*)&As[k][ty * 8 + 4];
            float4 b0 = *(const float4*)&Bs[k][tx * 8];
            float4 b1 = *(const float4*)&Bs[k][tx * 8 + 4];
            float a[8] = {a0.x, a0.y, a0.z, a0.w, a1.x, a1.y, a1.z, a1.w};
            float b[8] = {b0.x, b0.y, b0.z, b0.w, b1.x, b1.y, b1.z, b1.w};
#pragma unroll
            for (int i = 0; i < 8; i++)
#pragma unroll
                for (int j = 0; j < 8; j++)
                    acc[i][j] = fmaf(a[i], b[j], acc[i][j]);
        }
        __syncthreads();
    }

#pragma unroll
    for (int i = 0; i < 8; i++) {
        float* Cp = C + (long)(m0 + ty * 8 + i) * N + n0 + tx * 8;
        float4 c0 = make_float4(acc[i][0] * alpha, acc[i][1] * alpha,
                                acc[i][2] * alpha, acc[i][3] * alpha);
        float4 c1 = make_float4(acc[i][4] * alpha, acc[i][5] * alpha,
                                acc[i][6] * alpha, acc[i][7] * alpha);
        *(float4*)Cp       = c0;
        *(float4*)(Cp + 4) = c1;
    }
}

// ---------------------------------------------------------------------------
// kernel_launch: x, wq, wk, wv, wo  ->  out [B,S,D] fp32
// ---------------------------------------------------------------------------
extern "C" void kernel_launch(void* const* d_in, const int* in_sizes, int n_in,
                              void* d_out, int out_size) {
    const float* x  = (const float*)d_in[0];
    const float* wq = (const float*)d_in[1];
    const float* wk = (const float*)d_in[2];
    const float* wv = (const float*)d_in[3];
    const float* wo = (const float*)d_in[4];
    float* out = (float*)d_out;

    float *Q, *K, *V, *O, *P, *CT, *ST;
    cudaGetSymbolAddress((void**)&Q,  g_Q);
    cudaGetSymbolAddress((void**)&K,  g_K);
    cudaGetSymbolAddress((void**)&V,  g_V);
    cudaGetSymbolAddress((void**)&O,  g_O);
    cudaGetSymbolAddress((void**)&P,  g_P);
    cudaGetSymbolAddress((void**)&CT, g_cos);
    cudaGetSymbolAddress((void**)&ST, g_sin);

    const long SD = (long)SS * DD;     // per-batch Q/K/V/O stride
    const long SSs = (long)SS * SS;    // per-batch score stride

    // RoPE tables
    rope_table_kernel<<<SS, HALF>>>(CT, ST);

    // Q/K/V projections: [B*S, D] = x[B*S, D] @ W[D, D]^T
    dim3 gProj(DD / 128, (BB * SS) / 128, 1);
    sgemm_kernel<true><<<gProj, 256>>>(x, wq, Q, BB * SS, DD, DD, 0, 0, 0, 1.0f);
    sgemm_kernel<true><<<gProj, 256>>>(x, wk, K, BB * SS, DD, DD, 0, 0, 0, 1.0f);
    sgemm_kernel<true><<<gProj, 256>>>(x, wv, V, BB * SS, DD, DD, 0, 0, 0, 1.0f);

    // RoPE on Q, K
    rope_apply_kernel<<<BB * SS, HALF>>>(Q, K, CT, ST);

    // scores = (Q @ K^T) / 32, batched over B
    dim3 gScore(SS / 128, SS / 128, BB);
    sgemm_kernel<true><<<gScore, 256>>>(Q, K, P, SS, SS, DD, SD, SD, SSs, 0.03125f);

    // softmax rows
    softmax_kernel<<<BB * SS, 256>>>(P);

    // O = P @ V  (NN), batched
    dim3 gPV(DD / 128, SS / 128, BB);
    sgemm_kernel<false><<<gPV, 256>>>(P, V, O, SS, DD, SS, SSs, SD, SD, 1.0f);

    // out = O @ wo^T
    sgemm_kernel<true><<<gProj, 256>>>(O, wo, out, BB * SS, DD, DD, 0, 0, 0, 1.0f);
}

// round 12
// speedup vs baseline: 2.4884x; 2.4884x over previous
#include <cuda_runtime.h>
#include <math.h>
#include <stdint.h>

// Problem constants: x[4,2048,1024], weights [1024,1024]
#define BB   4
#define SS   2048
#define DD   1024
#define HALF (DD / 2)

// ---------------------------------------------------------------------------
// Scratch (device globals — no cudaMalloc allowed)
// ---------------------------------------------------------------------------
__device__ float g_Q[BB * SS * DD];
__device__ float g_K[BB * SS * DD];
__device__ float g_V[BB * SS * DD];
__device__ float g_O[BB * SS * DD];
__device__ float g_P[(long)BB * SS * SS];   // attention scores / probs
__device__ float g_cos[SS * HALF];
__device__ float g_sin[SS * HALF];

// ---------------------------------------------------------------------------
// RoPE cos/sin tables.  grid = SS, block = HALF
// ---------------------------------------------------------------------------
__global__ void rope_table_kernel(float* __restrict__ ct, float* __restrict__ st) {
    int s = blockIdx.x;
    int p = threadIdx.x;
    double inv = exp(-((double)(2 * p) / (double)DD) * log(10000.0));
    double ang = (double)s * inv;
    ct[s * HALF + p] = (float)cos(ang);
    st[s * HALF + p] = (float)sin(ang);
}

// ---------------------------------------------------------------------------
// Apply interleaved RoPE to Q and K in place.  grid = BB*SS, block = HALF
// ---------------------------------------------------------------------------
__global__ void rope_apply_kernel(float* __restrict__ q, float* __restrict__ k,
                                  const float* __restrict__ ct,
                                  const float* __restrict__ st) {
    int s = blockIdx.x & (SS - 1);
    long off = (long)blockIdx.x * DD + 2 * threadIdx.x;
    float c  = ct[s * HALF + threadIdx.x];
    float sn = st[s * HALF + threadIdx.x];
    float2 qv = *(float2*)(q + off);
    float2 kv = *(float2*)(k + off);
    float2 qo = make_float2(qv.x * c - qv.y * sn, qv.x * sn + qv.y * c);
    float2 ko = make_float2(kv.x * c - kv.y * sn, kv.x * sn + kv.y * c);
    *(float2*)(q + off) = qo;
    *(float2*)(k + off) = ko;
}

// ---------------------------------------------------------------------------
// Row softmax over length SS.  grid = BB*SS rows, block = 256
// ---------------------------------------------------------------------------
__global__ void softmax_kernel(float* __restrict__ P) {
    float* row = P + (long)blockIdx.x * SS;
    int t = threadIdx.x;
    float v[8];
    float m = -1e30f;
#pragma unroll
    for (int j = 0; j < 8; j++) {
        v[j] = row[t + 256 * j];
        m = fmaxf(m, v[j]);
    }
    __shared__ float red[8];
#pragma unroll
    for (int o = 16; o > 0; o >>= 1)
        m = fmaxf(m, __shfl_xor_sync(0xffffffffu, m, o));
    if ((t & 31) == 0) red[t >> 5] = m;
    __syncthreads();
    m = red[0];
#pragma unroll
    for (int i = 1; i < 8; i++) m = fmaxf(m, red[i]);

    float sum = 0.f;
#pragma unroll
    for (int j = 0; j < 8; j++) {
        v[j] = expf(v[j] - m);
        sum += v[j];
    }
#pragma unroll
    for (int o = 16; o > 0; o >>= 1)
        sum += __shfl_xor_sync(0xffffffffu, sum, o);
    __syncthreads();
    if ((t & 31) == 0) red[t >> 5] = sum;
    __syncthreads();
    sum = 0.f;
#pragma unroll
    for (int i = 0; i < 8; i++) sum += red[i];
    float inv = 1.0f / sum;
#pragma unroll
    for (int j = 0; j < 8; j++) row[t + 256 * j] = v[j] * inv;
}

// ---------------------------------------------------------------------------
// TF32 tensor-core GEMM.  128x128 CTA tile, BK=16, double-buffered smem,
// 8 warps in 2(m) x 4(n) grid, 64x32 warp tile, mma.sync.m16n8k8.tf32.
//   BT = true : C = alpha * A[M,K] @ B[N,K]^T   (A, B both K-contiguous)
//   BT = false: C = alpha * A[M,K] @ B[K,N]     (B is N-contiguous)
// M, N divisible by 128; K divisible by 16.   grid = (N/128, M/128, batch)
// ---------------------------------------------------------------------------
__device__ __forceinline__ uint32_t f2tf(float f) {
    uint32_t u;
    asm("cvt.rna.tf32.f32 %0, %1;" : "=r"(u) : "f"(f));
    return u;
}

template <bool BT>
__global__ void __launch_bounds__(256)
tf32_gemm(const float* __restrict__ A, const float* __restrict__ Bm,
          float* __restrict__ C, int M, int N, int K,
          long sA, long sB, long sC, float alpha) {
    A  += (long)blockIdx.z * sA;
    Bm += (long)blockIdx.z * sB;
    C  += (long)blockIdx.z * sC;
    const int m0 = blockIdx.y * 128;
    const int n0 = blockIdx.x * 128;

    // Padded strides for conflict-free fragment LDS:
    //   [row][k] tiles: stride 20 floats -> bank (20r + c) % 32 distinct
    //   [k][n]  tile (NN B): stride 136 -> bank (8k + n) % 32 distinct
    constexpr int AS_STRIDE = 20;
    constexpr int BS_STRIDE = BT ? 20 : 136;
    constexpr int BS_ELEMS  = BT ? 128 * 20 : 16 * 136;

    __shared__ __align__(16) float As[2][128 * AS_STRIDE];
    __shared__ __align__(16) float Bs[2][BS_ELEMS];

    const int t    = threadIdx.x;
    const int lane = t & 31;
    const int warp = t >> 5;
    const int wm   = warp & 1;   // m-tile offset wm*64
    const int wn   = warp >> 1;  // n-tile offset wn*32
    const int g    = lane >> 2;  // group id 0..7
    const int tg   = lane & 3;   // thread-in-group 0..3

    float acc[4][4][4];
#pragma unroll
    for (int i = 0; i < 4; i++)
#pragma unroll
        for (int j = 0; j < 4; j++)
#pragma unroll
            for (int r = 0; r < 4; r++) acc[i][j][r] = 0.f;

    // Global load descriptors (2 float4 per thread per operand per chunk)
    int aRow[2], aC4[2];
#pragma unroll
    for (int r = 0; r < 2; r++) {
        int id = t + 256 * r;
        aRow[r] = id >> 2;      // 0..127
        aC4[r]  = id & 3;       // float4 index within BK=16
    }
    int bRowNN[2], bC4NN[2];
#pragma unroll
    for (int r = 0; r < 2; r++) {
        int id = t + 256 * r;
        bRowNN[r] = id >> 5;    // 0..15
        bC4NN[r]  = id & 31;    // 0..31
    }

    const int nk = K / 16;
    float4 ra[2], rb[2];

    // ---- prologue: fetch chunk 0 ----
#pragma unroll
    for (int r = 0; r < 2; r++) {
        ra[r] = *(const float4*)(A + (long)(m0 + aRow[r]) * K + aC4[r] * 4);
        if (BT)
            rb[r] = *(const float4*)(Bm + (long)(n0 + aRow[r]) * K + aC4[r] * 4);
        else
            rb[r] = *(const float4*)(Bm + (long)bRowNN[r] * N + n0 + bC4NN[r] * 4);
    }
#pragma unroll
    for (int r = 0; r < 2; r++) {
        uint4 av = make_uint4(f2tf(ra[r].x), f2tf(ra[r].y), f2tf(ra[r].z), f2tf(ra[r].w));
        uint4 bv = make_uint4(f2tf(rb[r].x), f2tf(rb[r].y), f2tf(rb[r].z), f2tf(rb[r].w));
        *(uint4*)&As[0][aRow[r] * AS_STRIDE + aC4[r] * 4] = av;
        if (BT) *(uint4*)&Bs[0][aRow[r] * 20 + aC4[r] * 4] = bv;
        else    *(uint4*)&Bs[0][bRowNN[r] * 136 + bC4NN[r] * 4] = bv;
    }
    __syncthreads();

    int buf = 0;
    for (int kb = 0; kb < nk; kb++) {
        const bool more = (kb + 1 < nk);
        // ---- issue next chunk's global loads early ----
        if (more) {
            const int ko = (kb + 1) * 16;
#pragma unroll
            for (int r = 0; r < 2; r++) {
                ra[r] = *(const float4*)(A + (long)(m0 + aRow[r]) * K + ko + aC4[r] * 4);
                if (BT)
                    rb[r] = *(const float4*)(Bm + (long)(n0 + aRow[r]) * K + ko + aC4[r] * 4);
                else
                    rb[r] = *(const float4*)(Bm + (long)(ko + bRowNN[r]) * N + n0 + bC4NN[r] * 4);
            }
        }

        // ---- compute 2 k8-steps from current buffer ----
#pragma unroll
        for (int ks = 0; ks < 2; ks++) {
            uint32_t af[4][4], bf[4][2];
            const int c0 = ks * 8 + tg;
            const int r0 = wm * 64 + g;
#pragma unroll
            for (int i = 0; i < 4; i++) {
                const float* p = &As[buf][(r0 + i * 16) * AS_STRIDE + c0];
                af[i][0] = __float_as_uint(p[0]);
                af[i][1] = __float_as_uint(p[8 * AS_STRIDE]);
                af[i][2] = __float_as_uint(p[4]);
                af[i][3] = __float_as_uint(p[8 * AS_STRIDE + 4]);
            }
#pragma unroll
            for (int j = 0; j < 4; j++) {
                const int col = wn * 32 + j * 8 + g;
                if (BT) {
                    bf[j][0] = __float_as_uint(Bs[buf][col * 20 + c0]);
                    bf[j][1] = __float_as_uint(Bs[buf][col * 20 + c0 + 4]);
                } else {
                    bf[j][0] = __float_as_uint(Bs[buf][c0 * 136 + col]);
                    bf[j][1] = __float_as_uint(Bs[buf][(c0 + 4) * 136 + col]);
                }
            }
#pragma unroll
            for (int i = 0; i < 4; i++)
#pragma unroll
                for (int j = 0; j < 4; j++) {
                    asm volatile(
                        "mma.sync.aligned.m16n8k8.row.col.f32.tf32.tf32.f32 "
                        "{%0,%1,%2,%3}, {%4,%5,%6,%7}, {%8,%9}, {%0,%1,%2,%3};"
                        : "+f"(acc[i][j][0]), "+f"(acc[i][j][1]),
                          "+f"(acc[i][j][2]), "+f"(acc[i][j][3])
                        : "r"(af[i][0]), "r"(af[i][1]), "r"(af[i][2]), "r"(af[i][3]),
                          "r"(bf[j][0]), "r"(bf[j][1]));
                }
        }

        // ---- stage next chunk into the other buffer ----
        if (more) {
            const int nb = buf ^ 1;
#pragma unroll
            for (int r = 0; r < 2; r++) {
                uint4 av = make_uint4(f2tf(ra[r].x), f2tf(ra[r].y), f2tf(ra[r].z), f2tf(ra[r].w));
                uint4 bv = make_uint4(f2tf(rb[r].x), f2tf(rb[r].y), f2tf(rb[r].z), f2tf(rb[r].w));
                *(uint4*)&As[nb][aRow[r] * AS_STRIDE + aC4[r] * 4] = av;
                if (BT) *(uint4*)&Bs[nb][aRow[r] * 20 + aC4[r] * 4] = bv;
                else    *(uint4*)&Bs[nb][bRowNN[r] * 136 + bC4NN[r] * 4] = bv;
            }
        }
        __syncthreads();
        buf ^= 1;
    }

    // ---- epilogue ----
#pragma unroll
    for (int i = 0; i < 4; i++)
#pragma unroll
        for (int j = 0; j < 4; j++) {
            const int row = m0 + wm * 64 + i * 16 + g;
            const int col = n0 + wn * 32 + j * 8 + 2 * tg;
            float2 v0 = make_float2(acc[i][j][0] * alpha, acc[i][j][1] * alpha);
            float2 v1 = make_float2(acc[i][j][2] * alpha, acc[i][j][3] * alpha);
            *(float2*)(C + (long)row * N + col)       = v0;
            *(float2*)(C + (long)(row + 8) * N + col) = v1;
        }
}

// ---------------------------------------------------------------------------
// kernel_launch: x, wq, wk, wv, wo  ->  out [B,S,D] fp32
// ---------------------------------------------------------------------------
extern "C" void kernel_launch(void* const* d_in, const int* in_sizes, int n_in,
                              void* d_out, int out_size) {
    const float* x  = (const float*)d_in[0];
    const float* wq = (const float*)d_in[1];
    const float* wk = (const float*)d_in[2];
    const float* wv = (const float*)d_in[3];
    const float* wo = (const float*)d_in[4];
    float* out = (float*)d_out;

    float *Q, *K, *V, *O, *P, *CT, *ST;
    cudaGetSymbolAddress((void**)&Q,  g_Q);
    cudaGetSymbolAddress((void**)&K,  g_K);
    cudaGetSymbolAddress((void**)&V,  g_V);
    cudaGetSymbolAddress((void**)&O,  g_O);
    cudaGetSymbolAddress((void**)&P,  g_P);
    cudaGetSymbolAddress((void**)&CT, g_cos);
    cudaGetSymbolAddress((void**)&ST, g_sin);

    const long SD  = (long)SS * DD;
    const long SSs = (long)SS * SS;

    rope_table_kernel<<<SS, HALF>>>(CT, ST);

    // Q/K/V projections: [B*S, D] = x @ W^T
    dim3 gProj(DD / 128, (BB * SS) / 128, 1);
    tf32_gemm<true><<<gProj, 256>>>(x, wq, Q, BB * SS, DD, DD, 0, 0, 0, 1.0f);
    tf32_gemm<true><<<gProj, 256>>>(x, wk, K, BB * SS, DD, DD, 0, 0, 0, 1.0f);
    tf32_gemm<true><<<gProj, 256>>>(x, wv, V, BB * SS, DD, DD, 0, 0, 0, 1.0f);

    rope_apply_kernel<<<BB * SS, HALF>>>(Q, K, CT, ST);

    // scores = (Q @ K^T) / 32, batched over B
    dim3 gScore(SS / 128, SS / 128, BB);
    tf32_gemm<true><<<gScore, 256>>>(Q, K, P, SS, SS, DD, SD, SD, SSs, 0.03125f);

    softmax_kernel<<<BB * SS, 256>>>(P);

    // O = P @ V  (NN), batched
    dim3 gPV(DD / 128, SS / 128, BB);
    tf32_gemm<false><<<gPV, 256>>>(P, V, O, SS, DD, SS, SSs, SD, SD, 1.0f);

    // out = O @ wo^T
    tf32_gemm<true><<<gProj, 256>>>(O, wo, out, BB * SS, DD, DD, 0, 0, 0, 1.0f);
}

// round 13
// speedup vs baseline: 3.0685x; 1.2331x over previous
#include <cuda_runtime.h>
#include <math.h>
#include <stdint.h>

// Problem constants: x[4,2048,1024], weights [1024,1024]
#define BB   4
#define SS   2048
#define DD   1024
#define HALF (DD / 2)

// ---------------------------------------------------------------------------
// Scratch (device globals — no cudaMalloc allowed)
// ---------------------------------------------------------------------------
__device__ float g_Q[BB * SS * DD];
__device__ float g_K[BB * SS * DD];
__device__ float g_V[BB * SS * DD];
__device__ float g_O[BB * SS * DD];
__device__ float g_Xr[BB * SS * DD];          // tf32-rounded x
__device__ float g_Wr[4 * DD * DD];           // tf32-rounded wq,wk,wv,wo
__device__ float g_P[(long)BB * SS * SS];     // attention scores / probs
__device__ float g_cos[SS * HALF];
__device__ float g_sin[SS * HALF];

__device__ __forceinline__ uint32_t f2tf(float f) {
    uint32_t u;
    asm("cvt.rna.tf32.f32 %0, %1;" : "=r"(u) : "f"(f));
    return u;
}
__device__ __forceinline__ float rtf(float f) { return __uint_as_float(f2tf(f)); }

// ---------------------------------------------------------------------------
// Elementwise tf32 rounding (float4 vectorized). grid-stride free.
// ---------------------------------------------------------------------------
__global__ void round_tf32_kernel(const float* __restrict__ in,
                                  float* __restrict__ out, int n4) {
    int i = blockIdx.x * blockDim.x + threadIdx.x;
    if (i < n4) {
        float4 v = ((const float4*)in)[i];
        v.x = rtf(v.x); v.y = rtf(v.y); v.z = rtf(v.z); v.w = rtf(v.w);
        ((float4*)out)[i] = v;
    }
}

// ---------------------------------------------------------------------------
// RoPE cos/sin tables.  grid = SS, block = HALF
// ---------------------------------------------------------------------------
__global__ void rope_table_kernel(float* __restrict__ ct, float* __restrict__ st) {
    int s = blockIdx.x;
    int p = threadIdx.x;
    double inv = exp(-((double)(2 * p) / (double)DD) * log(10000.0));
    double ang = (double)s * inv;
    ct[s * HALF + p] = (float)cos(ang);
    st[s * HALF + p] = (float)sin(ang);
}

// ---------------------------------------------------------------------------
// Apply interleaved RoPE to Q and K in place; outputs tf32-rounded.
// grid = BB*SS, block = HALF
// ---------------------------------------------------------------------------
__global__ void rope_apply_kernel(float* __restrict__ q, float* __restrict__ k,
                                  const float* __restrict__ ct,
                                  const float* __restrict__ st) {
    int s = blockIdx.x & (SS - 1);
    long off = (long)blockIdx.x * DD + 2 * threadIdx.x;
    float c  = ct[s * HALF + threadIdx.x];
    float sn = st[s * HALF + threadIdx.x];
    float2 qv = *(float2*)(q + off);
    float2 kv = *(float2*)(k + off);
    float2 qo = make_float2(rtf(qv.x * c - qv.y * sn), rtf(qv.x * sn + qv.y * c));
    float2 ko = make_float2(rtf(kv.x * c - kv.y * sn), rtf(kv.x * sn + kv.y * c));
    *(float2*)(q + off) = qo;
    *(float2*)(k + off) = ko;
}

// ---------------------------------------------------------------------------
// Row softmax over length SS; outputs tf32-rounded. grid = BB*SS, block = 256
// ---------------------------------------------------------------------------
__global__ void softmax_kernel(float* __restrict__ P) {
    float* row = P + (long)blockIdx.x * SS;
    int t = threadIdx.x;
    float v[8];
    float m = -1e30f;
#pragma unroll
    for (int j = 0; j < 8; j++) {
        v[j] = row[t + 256 * j];
        m = fmaxf(m, v[j]);
    }
    __shared__ float red[8];
#pragma unroll
    for (int o = 16; o > 0; o >>= 1)
        m = fmaxf(m, __shfl_xor_sync(0xffffffffu, m, o));
    if ((t & 31) == 0) red[t >> 5] = m;
    __syncthreads();
    m = red[0];
#pragma unroll
    for (int i = 1; i < 8; i++) m = fmaxf(m, red[i]);

    float sum = 0.f;
#pragma unroll
    for (int j = 0; j < 8; j++) {
        v[j] = expf(v[j] - m);
        sum += v[j];
    }
#pragma unroll
    for (int o = 16; o > 0; o >>= 1)
        sum += __shfl_xor_sync(0xffffffffu, sum, o);
    __syncthreads();
    if ((t & 31) == 0) red[t >> 5] = sum;
    __syncthreads();
    sum = 0.f;
#pragma unroll
    for (int i = 0; i < 8; i++) sum += red[i];
    float inv = 1.0f / sum;
#pragma unroll
    for (int j = 0; j < 8; j++) row[t + 256 * j] = rtf(v[j] * inv);
}

// ---------------------------------------------------------------------------
// TF32 tensor-core GEMM, cp.async 3-stage pipeline.
// 128x128 CTA tile, BK=16, 8 warps (2m x 4n), 64x32 warp tiles,
// mma.sync.m16n8k8.tf32. Inputs MUST be pre-rounded to tf32 (hardware
// truncation then exact).
//   BT = true : C = alpha * A[M,K] @ B[N,K]^T
//   BT = false: C = alpha * A[M,K] @ B[K,N]
// M,N % 128 == 0; K % 16 == 0, K >= 32. grid = (N/128, M/128, batch)
// ---------------------------------------------------------------------------
#define CP16(dst_u32, src_ptr) \
    asm volatile("cp.async.cg.shared.global [%0], [%1], 16;" \
                 :: "r"(dst_u32), "l"(src_ptr))
#define CP_COMMIT() asm volatile("cp.async.commit_group;")
#define CP_WAIT1()  asm volatile("cp.async.wait_group 1;")

template <bool BT>
__global__ void __launch_bounds__(256)
tf32_gemm(const float* __restrict__ A, const float* __restrict__ Bm,
          float* __restrict__ C, int M, int N, int K,
          long sA, long sB, long sC, float alpha, int roundOut) {
    A  += (long)blockIdx.z * sA;
    Bm += (long)blockIdx.z * sB;
    C  += (long)blockIdx.z * sC;
    const int m0 = blockIdx.y * 128;
    const int n0 = blockIdx.x * 128;

    // Conflict-free padded strides (verified):
    //   [row][k] tiles: stride 20 -> bank (20r + c) % 32 all-distinct
    //   [k][n]  tile (NN B): stride 136 -> bank (8k + n) % 32 all-distinct
    constexpr int A_STAGE = 128 * 20;                  // floats per stage
    constexpr int B_STAGE = BT ? 128 * 20 : 16 * 136;

    extern __shared__ float smem[];
    float* AsAll = smem;                 // 3 stages
    float* BsAll = smem + 3 * A_STAGE;   // 3 stages

    uint32_t smem_u32;
    asm("{ .reg .u64 t; cvta.to.shared.u64 t, %1; cvt.u32.u64 %0, t; }"
        : "=r"(smem_u32) : "l"(smem));
    const uint32_t asBase = smem_u32;
    const uint32_t bsBase = smem_u32 + 3u * A_STAGE * 4u;

    const int t    = threadIdx.x;
    const int lane = t & 31;
    const int warp = t >> 5;
    const int wm   = warp & 1;
    const int wn   = warp >> 1;
    const int g    = lane >> 2;
    const int tg   = lane & 3;

    float acc[4][4][4];
#pragma unroll
    for (int i = 0; i < 4; i++)
#pragma unroll
        for (int j = 0; j < 4; j++)
#pragma unroll
            for (int r = 0; r < 4; r++) acc[i][j][r] = 0.f;

    // per-thread copy descriptors (2 x 16B per operand per stage)
    int aRow[2], aC4[2], bRowNN[2], bC4NN[2];
#pragma unroll
    for (int r = 0; r < 2; r++) {
        int id = t + 256 * r;
        aRow[r]   = id >> 2;   // 0..127
        aC4[r]    = id & 3;    // 0..3
        bRowNN[r] = id >> 5;   // 0..15
        bC4NN[r]  = id & 31;   // 0..31
    }

    const int nk = K / 16;

    auto issue = [&](int kb_, int st) {
        const int ko = kb_ * 16;
#pragma unroll
        for (int r = 0; r < 2; r++) {
            const float* srcA = A + (long)(m0 + aRow[r]) * K + ko + aC4[r] * 4;
            uint32_t dA = asBase + (uint32_t)(st * A_STAGE + aRow[r] * 20 + aC4[r] * 4) * 4u;
            CP16(dA, srcA);
            if (BT) {
                const float* srcB = Bm + (long)(n0 + aRow[r]) * K + ko + aC4[r] * 4;
                uint32_t dB = bsBase + (uint32_t)(st * B_STAGE + aRow[r] * 20 + aC4[r] * 4) * 4u;
                CP16(dB, srcB);
            } else {
                const float* srcB = Bm + (long)(ko + bRowNN[r]) * N + n0 + bC4NN[r] * 4;
                uint32_t dB = bsBase + (uint32_t)(st * B_STAGE + bRowNN[r] * 136 + bC4NN[r] * 4) * 4u;
                CP16(dB, srcB);
            }
        }
        CP_COMMIT();
    };

    // prologue: stages 0,1  (K >= 32 always here)
    issue(0, 0);
    issue(1, 1);
    CP_WAIT1();
    __syncthreads();

    int buf = 0;
    for (int kb = 0; kb < nk; kb++) {
        const float* AsB = AsAll + buf * A_STAGE;
        const float* BsB = BsAll + buf * B_STAGE;

#pragma unroll
        for (int ks = 0; ks < 2; ks++) {
            uint32_t af[4][4], bf[4][2];
            const int c0 = ks * 8 + tg;
            const int r0 = wm * 64 + g;
#pragma unroll
            for (int i = 0; i < 4; i++) {
                const float* p = &AsB[(r0 + i * 16) * 20 + c0];
                af[i][0] = __float_as_uint(p[0]);
                af[i][1] = __float_as_uint(p[8 * 20]);
                af[i][2] = __float_as_uint(p[4]);
                af[i][3] = __float_as_uint(p[8 * 20 + 4]);
            }
#pragma unroll
            for (int j = 0; j < 4; j++) {
                const int col = wn * 32 + j * 8 + g;
                if (BT) {
                    bf[j][0] = __float_as_uint(BsB[col * 20 + c0]);
                    bf[j][1] = __float_as_uint(BsB[col * 20 + c0 + 4]);
                } else {
                    bf[j][0] = __float_as_uint(BsB[c0 * 136 + col]);
                    bf[j][1] = __float_as_uint(BsB[(c0 + 4) * 136 + col]);
                }
            }
#pragma unroll
            for (int i = 0; i < 4; i++)
#pragma unroll
                for (int j = 0; j < 4; j++) {
                    asm volatile(
                        "mma.sync.aligned.m16n8k8.row.col.f32.tf32.tf32.f32 "
                        "{%0,%1,%2,%3}, {%4,%5,%6,%7}, {%8,%9}, {%0,%1,%2,%3};"
                        : "+f"(acc[i][j][0]), "+f"(acc[i][j][1]),
                          "+f"(acc[i][j][2]), "+f"(acc[i][j][3])
                        : "r"(af[i][0]), "r"(af[i][1]), "r"(af[i][2]), "r"(af[i][3]),
                          "r"(bf[j][0]), "r"(bf[j][1]));
                }
        }

        if (kb + 2 < nk) issue(kb + 2, (kb + 2) % 3);
        else             CP_COMMIT();   // empty group keeps wait arithmetic exact
        CP_WAIT1();
        __syncthreads();
        buf = (buf + 1) % 3 == 3 ? 0 : (buf + 1) % 3;
        // (simplify)
        if (buf >= 3) buf = 0;
    }

    // ---- epilogue ----
#pragma unroll
    for (int i = 0; i < 4; i++)
#pragma unroll
        for (int j = 0; j < 4; j++) {
            const int row = m0 + wm * 64 + i * 16 + g;
            const int col = n0 + wn * 32 + j * 8 + 2 * tg;
            float s0 = acc[i][j][0] * alpha, s1 = acc[i][j][1] * alpha;
            float s2 = acc[i][j][2] * alpha, s3 = acc[i][j][3] * alpha;
            if (roundOut) { s0 = rtf(s0); s1 = rtf(s1); s2 = rtf(s2); s3 = rtf(s3); }
            *(float2*)(C + (long)row * N + col)       = make_float2(s0, s1);
            *(float2*)(C + (long)(row + 8) * N + col) = make_float2(s2, s3);
        }
}

// ---------------------------------------------------------------------------
// kernel_launch: x, wq, wk, wv, wo  ->  out [B,S,D] fp32
// ---------------------------------------------------------------------------
extern "C" void kernel_launch(void* const* d_in, const int* in_sizes, int n_in,
                              void* d_out, int out_size) {
    const float* x  = (const float*)d_in[0];
    const float* w_in[4] = {(const float*)d_in[1], (const float*)d_in[2],
                            (const float*)d_in[3], (const float*)d_in[4]};
    float* out = (float*)d_out;

    float *Q, *K, *V, *O, *Xr, *Wr, *P, *CT, *ST;
    cudaGetSymbolAddress((void**)&Q,  g_Q);
    cudaGetSymbolAddress((void**)&K,  g_K);
    cudaGetSymbolAddress((void**)&V,  g_V);
    cudaGetSymbolAddress((void**)&O,  g_O);
    cudaGetSymbolAddress((void**)&Xr, g_Xr);
    cudaGetSymbolAddress((void**)&Wr, g_Wr);
    cudaGetSymbolAddress((void**)&P,  g_P);
    cudaGetSymbolAddress((void**)&CT, g_cos);
    cudaGetSymbolAddress((void**)&ST, g_sin);

    const long SD  = (long)SS * DD;
    const long SSs = (long)SS * SS;

    // dynamic smem sizes
    const int smemBT = 3 * (128 * 20 + 128 * 20) * 4;   // 61440
    const int smemNN = 3 * (128 * 20 + 16 * 136) * 4;   // 56832
    cudaFuncSetAttribute(tf32_gemm<true>,
                         cudaFuncAttributeMaxDynamicSharedMemorySize, smemBT);
    cudaFuncSetAttribute(tf32_gemm<false>,
                         cudaFuncAttributeMaxDynamicSharedMemorySize, smemNN);

    rope_table_kernel<<<SS, HALF>>>(CT, ST);

    // pre-round inputs to tf32
    {
        int n4 = BB * SS * DD / 4;
        round_tf32_kernel<<<(n4 + 255) / 256, 256>>>(x, Xr, n4);
        int w4 = DD * DD / 4;
        for (int i = 0; i < 4; i++)
            round_tf32_kernel<<<(w4 + 255) / 256, 256>>>(w_in[i], Wr + (long)i * DD * DD, w4);
    }
    const float* wq = Wr;
    const float* wk = Wr + (long)DD * DD;
    const float* wv = Wr + 2L * DD * DD;
    const float* wo = Wr + 3L * DD * DD;

    // Q/K/V projections: [B*S, D] = x @ W^T
    dim3 gProj(DD / 128, (BB * SS) / 128, 1);
    tf32_gemm<true><<<gProj, 256, smemBT>>>(Xr, wq, Q, BB * SS, DD, DD, 0, 0, 0, 1.0f, 0);
    tf32_gemm<true><<<gProj, 256, smemBT>>>(Xr, wk, K, BB * SS, DD, DD, 0, 0, 0, 1.0f, 0);
    tf32_gemm<true><<<gProj, 256, smemBT>>>(Xr, wv, V, BB * SS, DD, DD, 0, 0, 0, 1.0f, 1);

    // RoPE (rounds Q, K outputs)
    rope_apply_kernel<<<BB * SS, HALF>>>(Q, K, CT, ST);

    // scores = (Q @ K^T) / 32, batched over B
    dim3 gScore(SS / 128, SS / 128, BB);
    tf32_gemm<true><<<gScore, 256, smemBT>>>(Q, K, P, SS, SS, DD, SD, SD, SSs, 0.03125f, 0);

    softmax_kernel<<<BB * SS, 256>>>(P);   // rounds P

    // O = P @ V (NN), batched; round O for final GEMM
    dim3 gPV(DD / 128, SS / 128, BB);
    tf32_gemm<false><<<gPV, 256, smemNN>>>(P, V, O, SS, DD, SS, SSs, SD, SD, 1.0f, 1);

    // out = O @ wo^T
    tf32_gemm<true><<<gProj, 256, smemBT>>>(O, wo, out, BB * SS, DD, DD, 0, 0, 0, 1.0f, 0);
}